// round 1
// baseline (speedup 1.0000x reference)
#include <cuda_runtime.h>
#include <math.h>

// Problem constants
// B=8, N=1024, D=256, H=8, per-head d=256, HD=2048, M=1024, L=4
// rows BN = 8192, batch-heads BH = 64

// ---------------- static scratch (no allocation allowed) ----------------
__device__ float g_h [8192 * 256];          // 8 MB  : layernorm output
__device__ float g_q [64 * 1024 * 256];     // 64 MB : q [b*h, n, d]
__device__ float g_kk[64 * 1024 * 256];     // 64 MB : k
__device__ float g_v [64 * 1024 * 256];     // 64 MB : v
__device__ float g_e [64L * 1024 * 1024];   // 256 MB: energy / attn [b*h, n, n]
__device__ float g_o [8192 * 2048];         // 64 MB : attention out [b*n, HD]
__device__ float g_hm[8192 * 1024];         // 32 MB : mlp hidden

// ---------------- generic 128x128x8 SGEMM, templated epilogue ----------------
// MODE 0: plain store to C (ldc)                      [energy]
// MODE 1: +bias, scatter to g_q/g_kk/g_v              [qkv]
// MODE 2: C += acc + bias                             [proj, w2 residual]
// MODE 3: C = gelu(acc + bias)                        [w1]
// MODE 4: scatter to g_o as [b*n, HD]                 [attn @ v]
// TRANSB: B stored [Ncols, K] row-major (i.e. compute A @ B^T)
template<int MODE, bool TRANSB>
__global__ void __launch_bounds__(256, 2)
gemm_k(const float* __restrict__ A, const float* __restrict__ B,
       float* __restrict__ C, int K, int ldb, int ldc,
       const float* __restrict__ bias,
       long sA, long sB, long sC)
{
    __shared__ float As[8][128];
    __shared__ float Bs[8][128];

    const int z = blockIdx.z;
    A += (long)z * sA;
    B += (long)z * sB;
    if (C) C += (long)z * sC;

    const int tid     = threadIdx.x;
    const int rowBase = blockIdx.y * 128;
    const int colBase = blockIdx.x * 128;
    const int row0    = (tid >> 4) * 8;
    const int col0    = (tid & 15) * 8;

    float acc[8][8];
#pragma unroll
    for (int i = 0; i < 8; i++)
#pragma unroll
        for (int j = 0; j < 8; j++) acc[i][j] = 0.f;

    const int aRow = tid >> 1;          // 0..127
    const int aC4  = (tid & 1) * 4;     // 0 or 4
    const int bRow = tid >> 5;          // 0..7
    const int bCol = (tid & 31) * 4;    // 0..124

    for (int k0 = 0; k0 < K; k0 += 8) {
        float4 av = *reinterpret_cast<const float4*>(
            &A[(long)(rowBase + aRow) * K + k0 + aC4]);
        As[aC4 + 0][aRow] = av.x; As[aC4 + 1][aRow] = av.y;
        As[aC4 + 2][aRow] = av.z; As[aC4 + 3][aRow] = av.w;

        if (TRANSB) {
            float4 bv = *reinterpret_cast<const float4*>(
                &B[(long)(colBase + aRow) * ldb + k0 + aC4]);
            Bs[aC4 + 0][aRow] = bv.x; Bs[aC4 + 1][aRow] = bv.y;
            Bs[aC4 + 2][aRow] = bv.z; Bs[aC4 + 3][aRow] = bv.w;
        } else {
            float4 bv = *reinterpret_cast<const float4*>(
                &B[(long)(k0 + bRow) * ldb + colBase + bCol]);
            *reinterpret_cast<float4*>(&Bs[bRow][bCol]) = bv;
        }
        __syncthreads();

#pragma unroll
        for (int k = 0; k < 8; k++) {
            float4 a0 = *reinterpret_cast<const float4*>(&As[k][row0]);
            float4 a1 = *reinterpret_cast<const float4*>(&As[k][row0 + 4]);
            float4 b0 = *reinterpret_cast<const float4*>(&Bs[k][col0]);
            float4 b1 = *reinterpret_cast<const float4*>(&Bs[k][col0 + 4]);
            float a[8] = {a0.x, a0.y, a0.z, a0.w, a1.x, a1.y, a1.z, a1.w};
            float b[8] = {b0.x, b0.y, b0.z, b0.w, b1.x, b1.y, b1.z, b1.w};
#pragma unroll
            for (int i = 0; i < 8; i++)
#pragma unroll
                for (int j = 0; j < 8; j++)
                    acc[i][j] = fmaf(a[i], b[j], acc[i][j]);
        }
        __syncthreads();
    }

    const int gr = rowBase + row0;
    const int gc = colBase + col0;

    if (MODE == 0) {
#pragma unroll
        for (int i = 0; i < 8; i++) {
            float4 v0 = make_float4(acc[i][0], acc[i][1], acc[i][2], acc[i][3]);
            float4 v1 = make_float4(acc[i][4], acc[i][5], acc[i][6], acc[i][7]);
            *reinterpret_cast<float4*>(&C[(long)(gr + i) * ldc + gc])     = v0;
            *reinterpret_cast<float4*>(&C[(long)(gr + i) * ldc + gc + 4]) = v1;
        }
    } else if (MODE == 1) {
        // qkv reshape: col c -> which=c%3, dd=(c/3)%256, hh=(c/3)/256
        // row r -> b=r/1024, n=r%1024 ; dest [(b*8+hh)*1024+n]*256+dd
#pragma unroll
        for (int i = 0; i < 8; i++) {
            int r  = gr + i;
            int bb = r >> 10, n = r & 1023;
#pragma unroll
            for (int j = 0; j < 8; j++) {
                int   c     = gc + j;
                float val   = acc[i][j] + bias[c];
                int   which = c % 3;
                int   cc    = c / 3;
                int   dd    = cc & 255;
                int   hh    = cc >> 8;
                long  idx   = ((long)((bb << 3) + hh) * 1024 + n) * 256 + dd;
                float* dst  = (which == 0) ? g_q : (which == 1) ? g_kk : g_v;
                dst[idx] = val;
            }
        }
    } else if (MODE == 2) {
#pragma unroll
        for (int i = 0; i < 8; i++)
#pragma unroll
            for (int j = 0; j < 8; j++) {
                long idx = (long)(gr + i) * ldc + gc + j;
                C[idx] += acc[i][j] + bias[gc + j];
            }
    } else if (MODE == 3) {
#pragma unroll
        for (int i = 0; i < 8; i++)
#pragma unroll
            for (int j = 0; j < 8; j++) {
                float t = acc[i][j] + bias[gc + j];
                C[(long)(gr + i) * ldc + gc + j] =
                    0.5f * t * (1.f + erff(t * 0.70710678118654752f));
            }
    } else if (MODE == 4) {
        // z = b*8+h ; out g_o[(b*1024+n)*2048 + h*256 + col]
        int bb = z >> 3, hh = z & 7;
#pragma unroll
        for (int i = 0; i < 8; i++) {
            long base = ((long)(bb * 1024 + gr + i)) * 2048 + hh * 256 + gc;
            float4 v0 = make_float4(acc[i][0], acc[i][1], acc[i][2], acc[i][3]);
            float4 v1 = make_float4(acc[i][4], acc[i][5], acc[i][6], acc[i][7]);
            *reinterpret_cast<float4*>(&g_o[base])     = v0;
            *reinterpret_cast<float4*>(&g_o[base + 4]) = v1;
        }
    }
}

// ---------------- layernorm (biased var, eps=1e-5) ----------------
__global__ void ln_k(const float* __restrict__ x, const float* __restrict__ g,
                     const float* __restrict__ b, float* __restrict__ out)
{
    const int r = blockIdx.x, t = threadIdx.x;   // 256 threads, D=256
    float v  = x[(long)r * 256 + t];
    float s  = v, s2 = v * v;
#pragma unroll
    for (int o = 16; o; o >>= 1) {
        s  += __shfl_xor_sync(0xffffffffu, s,  o);
        s2 += __shfl_xor_sync(0xffffffffu, s2, o);
    }
    __shared__ float sh1[8], sh2[8];
    if ((t & 31) == 0) { sh1[t >> 5] = s; sh2[t >> 5] = s2; }
    __syncthreads();
    float ts = 0.f, ts2 = 0.f;
#pragma unroll
    for (int i = 0; i < 8; i++) { ts += sh1[i]; ts2 += sh2[i]; }
    float mean = ts * (1.f / 256.f);
    float var  = ts2 * (1.f / 256.f) - mean * mean;
    float inv  = rsqrtf(var + 1e-5f);
    out[(long)r * 256 + t] = (v - mean) * inv * g[t] + b[t];
}

// ---------------- softmax over rows of 1024, folds post-softmax /16 ----------------
__global__ void softmax_k(float* __restrict__ e)
{
    const long row = blockIdx.x;
    const int  t   = threadIdx.x;  // 256 threads * float4 = 1024
    float4* p = reinterpret_cast<float4*>(e) + row * 256 + t;
    float4 v  = *p;
    float m = fmaxf(fmaxf(v.x, v.y), fmaxf(v.z, v.w));
#pragma unroll
    for (int o = 16; o; o >>= 1) m = fmaxf(m, __shfl_xor_sync(0xffffffffu, m, o));
    __shared__ float shm[8], shs[8];
    if ((t & 31) == 0) shm[t >> 5] = m;
    __syncthreads();
    m = shm[0];
#pragma unroll
    for (int i = 1; i < 8; i++) m = fmaxf(m, shm[i]);
    float e0 = expf(v.x - m), e1 = expf(v.y - m);
    float e2 = expf(v.z - m), e3 = expf(v.w - m);
    float s = e0 + e1 + e2 + e3;
#pragma unroll
    for (int o = 16; o; o >>= 1) s += __shfl_xor_sync(0xffffffffu, s, o);
    if ((t & 31) == 0) shs[t >> 5] = s;
    __syncthreads();
    float ts = 0.f;
#pragma unroll
    for (int i = 0; i < 8; i++) ts += shs[i];
    float sc = 1.f / (ts * 16.f);     // post-softmax /scale folded in
    *p = make_float4(e0 * sc, e1 * sc, e2 * sc, e3 * sc);
}

// ---------------- driver ----------------
extern "C" void kernel_launch(void* const* d_in, const int* in_sizes, int n_in,
                              void* d_out, int out_size)
{
    const float* x_in   = (const float*)d_in[0];
    const float* ln1_g  = (const float*)d_in[1];
    const float* ln1_b  = (const float*)d_in[2];
    const float* qkv_w  = (const float*)d_in[3];
    const float* qkv_b  = (const float*)d_in[4];
    const float* proj_w = (const float*)d_in[5];
    const float* proj_b = (const float*)d_in[6];
    const float* ln2_g  = (const float*)d_in[7];
    const float* ln2_b  = (const float*)d_in[8];
    const float* w1     = (const float*)d_in[9];
    const float* b1     = (const float*)d_in[10];
    const float* w2     = (const float*)d_in[11];
    const float* b2     = (const float*)d_in[12];
    float* x = (float*)d_out;

    float *ph, *pq, *pk, *pv, *pe, *po, *pm;
    cudaGetSymbolAddress((void**)&ph, g_h);
    cudaGetSymbolAddress((void**)&pq, g_q);
    cudaGetSymbolAddress((void**)&pk, g_kk);
    cudaGetSymbolAddress((void**)&pv, g_v);
    cudaGetSymbolAddress((void**)&pe, g_e);
    cudaGetSymbolAddress((void**)&po, g_o);
    cudaGetSymbolAddress((void**)&pm, g_hm);

    cudaMemcpyAsync(x, x_in, (size_t)8192 * 256 * sizeof(float),
                    cudaMemcpyDeviceToDevice);

    for (int i = 0; i < 4; i++) {
        const float* qw  = qkv_w  + (long)i * 256 * 6144;
        const float* qb  = qkv_b  + i * 6144;
        const float* pw  = proj_w + (long)i * 2048 * 256;
        const float* pb  = proj_b + i * 256;
        const float* w1i = w1     + (long)i * 256 * 1024;
        const float* b1i = b1     + i * 1024;
        const float* w2i = w2     + (long)i * 1024 * 256;
        const float* b2i = b2     + i * 256;

        // attention block
        ln_k<<<8192, 256>>>(x, ln1_g + i * 256, ln1_b + i * 256, ph);
        gemm_k<1, false><<<dim3(48, 64, 1), 256>>>(
            ph, qw, nullptr, 256, 6144, 0, qb, 0, 0, 0);
        gemm_k<0, true><<<dim3(8, 8, 64), 256>>>(
            pq, pk, pe, 256, 256, 1024, nullptr,
            1024L * 256, 1024L * 256, 1024L * 1024);
        softmax_k<<<65536, 256>>>(pe);
        gemm_k<4, false><<<dim3(2, 8, 64), 256>>>(
            pe, pv, nullptr, 1024, 256, 0, nullptr,
            1024L * 1024, 1024L * 256, 0);
        gemm_k<2, false><<<dim3(2, 64, 1), 256>>>(
            po, pw, x, 2048, 256, 256, pb, 0, 0, 0);

        // MLP block
        ln_k<<<8192, 256>>>(x, ln2_g + i * 256, ln2_b + i * 256, ph);
        gemm_k<3, false><<<dim3(8, 64, 1), 256>>>(
            ph, w1i, pm, 256, 1024, 1024, b1i, 0, 0, 0);
        gemm_k<2, false><<<dim3(2, 64, 1), 256>>>(
            pm, w2i, x, 1024, 256, 256, b2i, 0, 0, 0);
    }
}

// round 5
// speedup vs baseline: 1.5889x; 1.5889x over previous
#include <cuda_runtime.h>
#include <cuda_bf16.h>
#include <math.h>

typedef __nv_bfloat16 BF16;

// B=8, N=1024, D=256, H=8, d_head=256, HD=2048, M=1024, L=4
// rows BN = 8192, batch-heads BH = 64

// ---------------- static scratch (all fp32; split to bf16 hi/lo at smem store) ----
__device__ float g_h [8192L * 256];          // LN output
__device__ float g_q [64L * 1024 * 256];
__device__ float g_k [64L * 1024 * 256];
__device__ float g_v [64L * 1024 * 256];
__device__ float g_e [64L * 1024 * 1024];    // energy / attn (softmax in-place)
__device__ float g_o [8192L * 2048];         // attention out [b*n, HD]
__device__ float g_hm[8192L * 1024];         // mlp hidden

// ---------------- mma helpers ----------------
__device__ __forceinline__ void ldmA(unsigned* r, unsigned addr) {
    asm volatile("ldmatrix.sync.aligned.m8n8.x4.shared.b16 {%0,%1,%2,%3}, [%4];"
                 : "=r"(r[0]), "=r"(r[1]), "=r"(r[2]), "=r"(r[3]) : "r"(addr));
}
__device__ __forceinline__ void ldmBT(unsigned* r, unsigned addr) {
    asm volatile("ldmatrix.sync.aligned.m8n8.x4.trans.shared.b16 {%0,%1,%2,%3}, [%4];"
                 : "=r"(r[0]), "=r"(r[1]), "=r"(r[2]), "=r"(r[3]) : "r"(addr));
}
__device__ __forceinline__ void mma16816(float* c, const unsigned* a, const unsigned* b) {
    asm volatile("mma.sync.aligned.m16n8k16.row.col.f32.bf16.bf16.f32 "
                 "{%0,%1,%2,%3}, {%4,%5,%6,%7}, {%8,%9}, {%0,%1,%2,%3};"
                 : "+f"(c[0]), "+f"(c[1]), "+f"(c[2]), "+f"(c[3])
                 : "r"(a[0]), "r"(a[1]), "r"(a[2]), "r"(a[3]),
                   "r"(b[0]), "r"(b[1]));
}

#define A_STRIDE 40
#define B_STRIDE 136

// split one float into bf16 hi/lo and store to two smem arrays (as ushort bits)
__device__ __forceinline__ void split_store(unsigned short* sh, unsigned short* sl,
                                            int idx, float x) {
    BF16 h = __float2bfloat16(x);
    float hf = __bfloat162float(h);
    BF16 l = __float2bfloat16(x - hf);
    ((BF16*)sh)[idx] = h;
    ((BF16*)sl)[idx] = l;
}

// ---------------- 128x128x32 3xBF16 tensor-core GEMM, templated epilogue --------
// MODE 0: fp32 store to C                    [energy]
// MODE 1: +bias, fp32 scatter to g_q/g_k/g_v [qkv]
// MODE 2: fp32 C += acc + bias               [proj, w2]
// MODE 3: fp32 C = gelu(acc+bias)            [w1]
// MODE 4: fp32 scatter to g_o                [attn@v]
// TRANSB: B stored [Ncols, K] row-major (compute A @ B^T)
template<int MODE, bool TRANSB>
__global__ void __launch_bounds__(256)
bgemm(const float* __restrict__ A, const float* __restrict__ B,
      float* __restrict__ C, int K, int ldb, int ldc,
      const float* __restrict__ bias, long sA, long sB, long sC)
{
    __shared__ unsigned short As_h[128 * A_STRIDE];
    __shared__ unsigned short As_l[128 * A_STRIDE];
    __shared__ unsigned short Bs_h[32 * B_STRIDE];
    __shared__ unsigned short Bs_l[32 * B_STRIDE];

    const int z = blockIdx.z;
    const float* Ag = A + (long)z * sA;
    const float* Bg = B + (long)z * sB;
    float* Cg = C ? C + (long)z * sC : (float*)0;

    const int tid  = threadIdx.x;
    const int lane = tid & 31;
    const int warp = tid >> 5;
    const int wm = warp >> 1;   // 0..3  row 32-blocks
    const int wn = warp & 1;    // 0..1  col 64-blocks
    const int rowBase = blockIdx.y * 128;
    const int colBase = blockIdx.x * 128;

    float acc[2][8][4];
#pragma unroll
    for (int i = 0; i < 2; i++)
#pragma unroll
        for (int j = 0; j < 8; j++)
#pragma unroll
            for (int e = 0; e < 4; e++) acc[i][j][e] = 0.f;

    const unsigned baseAh = (unsigned)__cvta_generic_to_shared(As_h);
    const unsigned baseAl = (unsigned)__cvta_generic_to_shared(As_l);
    const unsigned baseBh = (unsigned)__cvta_generic_to_shared(Bs_h);
    const unsigned baseBl = (unsigned)__cvta_generic_to_shared(Bs_l);

    const int nk = K >> 5;
    for (int kt = 0; kt < nk; kt++) {
        const int k0 = kt << 5;
        if (kt > 0) __syncthreads();   // previous tile fully consumed

        // ---- A tile: 128 x 32 fp32 -> hi/lo smem ----
#pragma unroll
        for (int u = 0; u < 4; u++) {
            int s   = tid + u * 256;        // 0..1023 float4 units
            int row = s >> 3;
            int c4  = (s & 7) << 2;
            float4 v = *(const float4*)&Ag[(long)(rowBase + row) * K + k0 + c4];
            int idx = row * A_STRIDE + c4;
            split_store(As_h, As_l, idx + 0, v.x);
            split_store(As_h, As_l, idx + 1, v.y);
            split_store(As_h, As_l, idx + 2, v.z);
            split_store(As_h, As_l, idx + 3, v.w);
        }
        // ---- B tile: 32 x 128 fp32 -> hi/lo smem (k-major) ----
#pragma unroll
        for (int u = 0; u < 4; u++) {
            int s = tid + u * 256;
            if (!TRANSB) {
                int kk = s >> 5;
                int c4 = (s & 31) << 2;
                float4 v = *(const float4*)&Bg[(long)(k0 + kk) * ldb + colBase + c4];
                int idx = kk * B_STRIDE + c4;
                split_store(Bs_h, Bs_l, idx + 0, v.x);
                split_store(Bs_h, Bs_l, idx + 1, v.y);
                split_store(Bs_h, Bs_l, idx + 2, v.z);
                split_store(Bs_h, Bs_l, idx + 3, v.w);
            } else {
                int n  = s >> 3;
                int k4 = (s & 7) << 2;
                float4 v = *(const float4*)&Bg[(long)(colBase + n) * ldb + k0 + k4];
                split_store(Bs_h, Bs_l, (k4 + 0) * B_STRIDE + n, v.x);
                split_store(Bs_h, Bs_l, (k4 + 1) * B_STRIDE + n, v.y);
                split_store(Bs_h, Bs_l, (k4 + 2) * B_STRIDE + n, v.z);
                split_store(Bs_h, Bs_l, (k4 + 3) * B_STRIDE + n, v.w);
            }
        }
        __syncthreads();

        // ---- compute: 2 x k16 steps, 3 mmas per (hi*hi, hi*lo, lo*hi) ----
#pragma unroll
        for (int ks = 0; ks < 2; ks++) {
            unsigned ah[2][4], al[2][4], bh[4][4], bl[4][4];
#pragma unroll
            for (int mi = 0; mi < 2; mi++) {
                unsigned off = (((wm * 32 + mi * 16 + (lane & 15)) * A_STRIDE)
                                + ks * 16 + ((lane >> 4) << 3)) << 1;
                ldmA(ah[mi], baseAh + off);
                ldmA(al[mi], baseAl + off);
            }
#pragma unroll
            for (int ni = 0; ni < 4; ni++) {
                unsigned off = (((ks * 16 + (lane & 15)) * B_STRIDE)
                                + wn * 64 + ni * 16 + ((lane >> 4) << 3)) << 1;
                ldmBT(bh[ni], baseBh + off);
                ldmBT(bl[ni], baseBl + off);
            }
#pragma unroll
            for (int mi = 0; mi < 2; mi++)
#pragma unroll
                for (int nb = 0; nb < 8; nb++) {
                    const unsigned* bhp = &bh[nb >> 1][(nb & 1) << 1];
                    const unsigned* blp = &bl[nb >> 1][(nb & 1) << 1];
                    mma16816(acc[mi][nb], ah[mi], bhp);
                    mma16816(acc[mi][nb], ah[mi], blp);
                    mma16816(acc[mi][nb], al[mi], bhp);
                }
        }
    }

    // ---------------- epilogue ----------------
    const int g  = lane >> 2;
    const int tg = lane & 3;
#pragma unroll
    for (int mi = 0; mi < 2; mi++)
#pragma unroll
        for (int nb = 0; nb < 8; nb++) {
            int r0 = rowBase + wm * 32 + mi * 16 + g;
            int c0 = colBase + wn * 64 + nb * 8 + tg * 2;
#pragma unroll
            for (int e = 0; e < 4; e++) {
                int gr = r0 + (e >> 1) * 8;
                int gc = c0 + (e & 1);
                float val = acc[mi][nb][e];
                if (MODE == 0) {
                    Cg[(long)gr * ldc + gc] = val;
                } else if (MODE == 1) {
                    float xv = val + bias[gc];
                    int which = gc % 3, cc = gc / 3;
                    int dd = cc & 255, hh = cc >> 8;
                    int bb = gr >> 10, n = gr & 1023;
                    long idx = ((long)((bb << 3) + hh) * 1024 + n) * 256 + dd;
                    if (which == 0)      g_q[idx] = xv;
                    else if (which == 1) g_k[idx] = xv;
                    else                 g_v[idx] = xv;
                } else if (MODE == 2) {
                    Cg[(long)gr * ldc + gc] += val + bias[gc];
                } else if (MODE == 3) {
                    float t = val + bias[gc];
                    Cg[(long)gr * ldc + gc] =
                        0.5f * t * (1.f + erff(t * 0.70710678118654752f));
                } else if (MODE == 4) {
                    int bb = z >> 3, hh = z & 7;
                    g_o[((long)(bb * 1024 + gr)) * 2048 + hh * 256 + gc] = val;
                }
            }
        }
}

// ---------------- layernorm (biased var, eps=1e-5) ----------------
__global__ void ln_k(const float* __restrict__ x, const float* __restrict__ g,
                     const float* __restrict__ b, float* __restrict__ out)
{
    const int r = blockIdx.x, t = threadIdx.x;   // 256 threads, D=256
    float v  = x[(long)r * 256 + t];
    float s  = v, s2 = v * v;
#pragma unroll
    for (int o = 16; o; o >>= 1) {
        s  += __shfl_xor_sync(0xffffffffu, s,  o);
        s2 += __shfl_xor_sync(0xffffffffu, s2, o);
    }
    __shared__ float sh1[8], sh2[8];
    if ((t & 31) == 0) { sh1[t >> 5] = s; sh2[t >> 5] = s2; }
    __syncthreads();
    float ts = 0.f, ts2 = 0.f;
#pragma unroll
    for (int i = 0; i < 8; i++) { ts += sh1[i]; ts2 += sh2[i]; }
    float mean = ts * (1.f / 256.f);
    float var  = ts2 * (1.f / 256.f) - mean * mean;
    float inv  = rsqrtf(var + 1e-5f);
    out[(long)r * 256 + t] = (v - mean) * inv * g[t] + b[t];
}

// ---------------- softmax over rows of 1024 (in place), folds /16 ----------------
__global__ void softmax_k(float* __restrict__ e)
{
    const long row = blockIdx.x;
    const int  t   = threadIdx.x;
    float4* p = reinterpret_cast<float4*>(e) + row * 256 + t;
    float4 v  = *p;
    float m = fmaxf(fmaxf(v.x, v.y), fmaxf(v.z, v.w));
#pragma unroll
    for (int o = 16; o; o >>= 1) m = fmaxf(m, __shfl_xor_sync(0xffffffffu, m, o));
    __shared__ float shm[8], shs[8];
    if ((t & 31) == 0) shm[t >> 5] = m;
    __syncthreads();
    m = shm[0];
#pragma unroll
    for (int i = 1; i < 8; i++) m = fmaxf(m, shm[i]);
    float e0 = expf(v.x - m), e1 = expf(v.y - m);
    float e2 = expf(v.z - m), e3 = expf(v.w - m);
    float s = e0 + e1 + e2 + e3;
#pragma unroll
    for (int o = 16; o; o >>= 1) s += __shfl_xor_sync(0xffffffffu, s, o);
    if ((t & 31) == 0) shs[t >> 5] = s;
    __syncthreads();
    float ts = 0.f;
#pragma unroll
    for (int i = 0; i < 8; i++) ts += shs[i];
    float sc = 1.f / (ts * 16.f);
    *p = make_float4(e0 * sc, e1 * sc, e2 * sc, e3 * sc);
}

// ---------------- driver ----------------
extern "C" void kernel_launch(void* const* d_in, const int* in_sizes, int n_in,
                              void* d_out, int out_size)
{
    const float* x_in   = (const float*)d_in[0];
    const float* ln1_g  = (const float*)d_in[1];
    const float* ln1_b  = (const float*)d_in[2];
    const float* qkv_w  = (const float*)d_in[3];
    const float* qkv_b  = (const float*)d_in[4];
    const float* proj_w = (const float*)d_in[5];
    const float* proj_b = (const float*)d_in[6];
    const float* ln2_g  = (const float*)d_in[7];
    const float* ln2_b  = (const float*)d_in[8];
    const float* w1     = (const float*)d_in[9];
    const float* b1     = (const float*)d_in[10];
    const float* w2     = (const float*)d_in[11];
    const float* b2     = (const float*)d_in[12];
    float* x = (float*)d_out;

    float *ph, *pq, *pk, *pv, *pe, *po, *pm;
    cudaGetSymbolAddress((void**)&ph, g_h);
    cudaGetSymbolAddress((void**)&pq, g_q);
    cudaGetSymbolAddress((void**)&pk, g_k);
    cudaGetSymbolAddress((void**)&pv, g_v);
    cudaGetSymbolAddress((void**)&pe, g_e);
    cudaGetSymbolAddress((void**)&po, g_o);
    cudaGetSymbolAddress((void**)&pm, g_hm);

    cudaMemcpyAsync(x, x_in, (size_t)8192 * 256 * sizeof(float),
                    cudaMemcpyDeviceToDevice);

    for (int i = 0; i < 4; i++) {
        const float* qw  = qkv_w  + (long)i * 256 * 6144;
        const float* qb  = qkv_b  + i * 6144;
        const float* pw  = proj_w + (long)i * 2048 * 256;
        const float* pb  = proj_b + i * 256;
        const float* w1i = w1     + (long)i * 256 * 1024;
        const float* b1i = b1     + i * 1024;
        const float* w2i = w2     + (long)i * 1024 * 256;
        const float* b2i = b2     + i * 256;

        // attention block
        ln_k<<<8192, 256>>>(x, ln1_g + i * 256, ln1_b + i * 256, ph);
        bgemm<1, false><<<dim3(48, 64, 1), 256>>>(
            ph, qw, (float*)0, 256, 6144, 0, qb, 0, 0, 0);
        bgemm<0, true><<<dim3(8, 8, 64), 256>>>(
            pq, pk, pe, 256, 256, 1024, (const float*)0,
            1024L * 256, 1024L * 256, 1024L * 1024);
        softmax_k<<<65536, 256>>>(pe);
        bgemm<4, false><<<dim3(2, 8, 64), 256>>>(
            pe, pv, (float*)0, 1024, 256, 0, (const float*)0,
            1024L * 1024, 1024L * 256, 0);
        bgemm<2, false><<<dim3(2, 64, 1), 256>>>(
            po, pw, x, 2048, 256, 256, pb, 0, 0, 0);

        // MLP block
        ln_k<<<8192, 256>>>(x, ln2_g + i * 256, ln2_b + i * 256, ph);
        bgemm<3, false><<<dim3(8, 64, 1), 256>>>(
            ph, w1i, pm, 256, 1024, 1024, b1i, 0, 0, 0);
        bgemm<2, false><<<dim3(2, 64, 1), 256>>>(
            pm, w2i, x, 1024, 256, 256, b2i, 0, 0, 0);
    }
}

// round 11
// speedup vs baseline: 1.8152x; 1.1424x over previous
#include <cuda_runtime.h>
#include <cuda_bf16.h>
#include <math.h>

typedef __nv_bfloat16 BF16;

// B=8, N=1024, D=256, H=8, d_head=256, HD=2048, M=1024, L=4
// rows BN = 8192, batch-heads BH = 64
// Round 8: clean resubmit of the round-6 kernel (infra failure, code untested).

// ---------------- static scratch ----------------
__device__ float g_e[64L * 1024 * 1024];     // 256 MB energy fp32
__device__ BF16 g_hh[8192L * 256];           // LN out hi
__device__ BF16 g_hl[8192L * 256];           // LN out lo
__device__ BF16 g_qh[64L * 1024 * 256];
__device__ BF16 g_ql[64L * 1024 * 256];
__device__ BF16 g_kh[64L * 1024 * 256];
__device__ BF16 g_kl[64L * 1024 * 256];
__device__ BF16 g_vh[64L * 1024 * 256];
__device__ BF16 g_vl[64L * 1024 * 256];
__device__ BF16 g_ah[64L * 1024 * 1024];     // attn hi
__device__ BF16 g_al[64L * 1024 * 1024];     // attn lo
__device__ BF16 g_oh[8192L * 2048];
__device__ BF16 g_ol[8192L * 2048];
__device__ BF16 g_mh[8192L * 1024];
__device__ BF16 g_ml[8192L * 1024];
__device__ BF16 g_wqh[4L * 256 * 6144];
__device__ BF16 g_wql[4L * 256 * 6144];
__device__ BF16 g_wph[4L * 2048 * 256];
__device__ BF16 g_wpl[4L * 2048 * 256];
__device__ BF16 g_w1h[4L * 256 * 1024];
__device__ BF16 g_w1l[4L * 256 * 1024];
__device__ BF16 g_w2h[4L * 1024 * 256];
__device__ BF16 g_w2l[4L * 1024 * 256];

// ---------------- asm helpers ----------------
__device__ __forceinline__ void ldm4(unsigned* r, unsigned addr) {
    asm volatile("ldmatrix.sync.aligned.m8n8.x4.shared.b16 {%0,%1,%2,%3}, [%4];"
                 : "=r"(r[0]), "=r"(r[1]), "=r"(r[2]), "=r"(r[3]) : "r"(addr));
}
__device__ __forceinline__ void ldm4t(unsigned* r, unsigned addr) {
    asm volatile("ldmatrix.sync.aligned.m8n8.x4.trans.shared.b16 {%0,%1,%2,%3}, [%4];"
                 : "=r"(r[0]), "=r"(r[1]), "=r"(r[2]), "=r"(r[3]) : "r"(addr));
}
__device__ __forceinline__ void mma16816(float* c, const unsigned* a,
                                         unsigned b0, unsigned b1) {
    asm volatile("mma.sync.aligned.m16n8k16.row.col.f32.bf16.bf16.f32 "
                 "{%0,%1,%2,%3}, {%4,%5,%6,%7}, {%8,%9}, {%0,%1,%2,%3};"
                 : "+f"(c[0]), "+f"(c[1]), "+f"(c[2]), "+f"(c[3])
                 : "r"(a[0]), "r"(a[1]), "r"(a[2]), "r"(a[3]),
                   "r"(b0), "r"(b1));
}
#define CPA(dst, src) asm volatile("cp.async.cg.shared.global [%0], [%1], 16;" :: "r"(dst), "l"(src))
#define CPC()  asm volatile("cp.async.commit_group;")
#define CPW0() asm volatile("cp.async.wait_group 0;")
#define CPW1() asm volatile("cp.async.wait_group 1;")

#define A_STRIDE 40
#define B_STRIDE 136
// smem byte layout per stage (stage stride 40960 B, total 81920 B):
//  +0      Ah  (128x40 bf16 = 10240 B)
//  +10240  Al
//  +20480  Bh  (32x136 or 128x40)
//  +30720  Bl
#define SMEM_BYTES 81920

// ---------------- 128x128x32 3xBF16 tensor-core GEMM, cp.async double-buffered --
// MODE 0: fp32 store to g_e                 [energy]
// MODE 1: +bias, hi/lo scatter to q/k/v     [qkv]
// MODE 2: fp32 C += acc + bias              [proj, w2]
// MODE 3: hi/lo gelu(acc+bias) -> g_mh/g_ml [w1]
// MODE 4: hi/lo scatter to g_oh/g_ol        [attn@v]
// TRANSB: B stored [Ncols, K] row-major (compute A @ B^T)
template<int MODE, bool TRANSB>
__global__ void __launch_bounds__(256)
bgemm(const BF16* __restrict__ Ah, const BF16* __restrict__ Al,
      const BF16* __restrict__ Bh, const BF16* __restrict__ Bl,
      float* __restrict__ C, int K, int ldb, int ldc,
      const float* __restrict__ bias, long sA, long sB, long sC)
{
    extern __shared__ unsigned short sm[];
    const unsigned smBase = (unsigned)__cvta_generic_to_shared(sm);

    const int z = blockIdx.z;
    const BF16* Agh = Ah + (long)z * sA;
    const BF16* Agl = Al + (long)z * sA;
    const BF16* Bgh = Bh + (long)z * sB;
    const BF16* Bgl = Bl + (long)z * sB;
    float* Cg = C ? C + (long)z * sC : (float*)0;

    const int tid  = threadIdx.x;
    const int lane = tid & 31;
    const int warp = tid >> 5;
    const int wm = warp >> 1;   // 0..3 row 32-blocks
    const int wn = warp & 1;    // 0..1 col 64-blocks
    const int rowBase = blockIdx.y * 128;
    const int colBase = blockIdx.x * 128;

    float acc[2][8][4];
#pragma unroll
    for (int i = 0; i < 2; i++)
#pragma unroll
        for (int j = 0; j < 8; j++)
#pragma unroll
            for (int e = 0; e < 4; e++) acc[i][j][e] = 0.f;

#define LOAD_TILE(k0, st) do {                                               \
    unsigned sb_ = smBase + (st) * 40960;                                    \
    _Pragma("unroll")                                                        \
    for (int u_ = 0; u_ < 2; u_++) {                                         \
        int c_ = tid + u_ * 256;                                             \
        int r_ = c_ >> 2, k8_ = (c_ & 3) << 3;                               \
        CPA(sb_ + ((r_ * A_STRIDE + k8_) << 1),                              \
            Agh + (long)(rowBase + r_) * K + (k0) + k8_);                    \
        CPA(sb_ + 10240 + ((r_ * A_STRIDE + k8_) << 1),                      \
            Agl + (long)(rowBase + r_) * K + (k0) + k8_);                    \
        if (TRANSB) {                                                        \
            CPA(sb_ + 20480 + ((r_ * A_STRIDE + k8_) << 1),                  \
                Bgh + (long)(colBase + r_) * ldb + (k0) + k8_);              \
            CPA(sb_ + 30720 + ((r_ * A_STRIDE + k8_) << 1),                  \
                Bgl + (long)(colBase + r_) * ldb + (k0) + k8_);              \
        } else {                                                             \
            int kk_ = c_ >> 4, n8_ = (c_ & 15) << 3;                         \
            CPA(sb_ + 20480 + ((kk_ * B_STRIDE + n8_) << 1),                 \
                Bgh + (long)((k0) + kk_) * ldb + colBase + n8_);             \
            CPA(sb_ + 30720 + ((kk_ * B_STRIDE + n8_) << 1),                 \
                Bgl + (long)((k0) + kk_) * ldb + colBase + n8_);             \
        }                                                                    \
    }                                                                        \
} while (0)

    const int nk = K >> 5;
    LOAD_TILE(0, 0);
    CPC();

    for (int kt = 0; kt < nk; kt++) {
        if (kt + 1 < nk) {
            LOAD_TILE((kt + 1) << 5, (kt + 1) & 1);
            CPC();
            CPW1();
        } else {
            CPW0();
        }
        __syncthreads();

        const unsigned sb = smBase + (kt & 1) * 40960;
#pragma unroll
        for (int ks = 0; ks < 2; ks++) {
            unsigned fah[2][4], fal[2][4], fbh[4][4], fbl[4][4];
#pragma unroll
            for (int mi = 0; mi < 2; mi++) {
                unsigned off = ((unsigned)((wm * 32 + mi * 16 + (lane & 15)) * A_STRIDE
                                + ks * 16 + ((lane >> 4) << 3))) << 1;
                ldm4(fah[mi], sb + off);
                ldm4(fal[mi], sb + 10240 + off);
            }
#pragma unroll
            for (int ni = 0; ni < 4; ni++) {
                if (TRANSB) {
                    unsigned off = ((unsigned)((wn * 64 + ni * 16 + (lane & 15)) * A_STRIDE
                                    + ks * 16 + ((lane >> 4) << 3))) << 1;
                    ldm4(fbh[ni], sb + 20480 + off);
                    ldm4(fbl[ni], sb + 30720 + off);
                } else {
                    unsigned off = ((unsigned)((ks * 16 + (lane & 15)) * B_STRIDE
                                    + wn * 64 + ni * 16 + ((lane >> 4) << 3))) << 1;
                    ldm4t(fbh[ni], sb + 20480 + off);
                    ldm4t(fbl[ni], sb + 30720 + off);
                }
            }
#pragma unroll
            for (int mi = 0; mi < 2; mi++)
#pragma unroll
                for (int nb = 0; nb < 8; nb++) {
                    int ti = nb >> 1;
                    unsigned b0h, b1h, b0l, b1l;
                    if (TRANSB) {
                        b0h = fbh[ti][nb & 1]; b1h = fbh[ti][(nb & 1) + 2];
                        b0l = fbl[ti][nb & 1]; b1l = fbl[ti][(nb & 1) + 2];
                    } else {
                        b0h = fbh[ti][(nb & 1) * 2]; b1h = fbh[ti][(nb & 1) * 2 + 1];
                        b0l = fbl[ti][(nb & 1) * 2]; b1l = fbl[ti][(nb & 1) * 2 + 1];
                    }
                    mma16816(acc[mi][nb], fah[mi], b0h, b1h);
                    mma16816(acc[mi][nb], fah[mi], b0l, b1l);
                    mma16816(acc[mi][nb], fal[mi], b0h, b1h);
                }
        }
        __syncthreads();
    }
#undef LOAD_TILE

    // ---------------- epilogue ----------------
    const int g  = lane >> 2;
    const int tg = lane & 3;
#pragma unroll
    for (int mi = 0; mi < 2; mi++)
#pragma unroll
        for (int nb = 0; nb < 8; nb++) {
            int r0 = rowBase + wm * 32 + mi * 16 + g;
            int c0 = colBase + wn * 64 + nb * 8 + tg * 2;
#pragma unroll
            for (int e = 0; e < 4; e++) {
                int gr = r0 + (e >> 1) * 8;
                int gc = c0 + (e & 1);
                float val = acc[mi][nb][e];
                if (MODE == 0) {
                    Cg[(long)gr * ldc + gc] = val;
                } else if (MODE == 1) {
                    float xv = val + bias[gc];
                    int which = gc % 3, cc = gc / 3;
                    int dd = cc & 255, hh = cc >> 8;
                    int bb = gr >> 10, n = gr & 1023;
                    long idx = ((long)((bb << 3) + hh) * 1024 + n) * 256 + dd;
                    BF16 hv = __float2bfloat16(xv);
                    BF16 lv = __float2bfloat16(xv - __bfloat162float(hv));
                    if (which == 0)      { g_qh[idx] = hv; g_ql[idx] = lv; }
                    else if (which == 1) { g_kh[idx] = hv; g_kl[idx] = lv; }
                    else                 { g_vh[idx] = hv; g_vl[idx] = lv; }
                } else if (MODE == 2) {
                    Cg[(long)gr * ldc + gc] += val + bias[gc];
                } else if (MODE == 3) {
                    float t = val + bias[gc];
                    float gv = 0.5f * t * (1.f + erff(t * 0.70710678118654752f));
                    long idx = (long)gr * ldc + gc;
                    BF16 hv = __float2bfloat16(gv);
                    g_mh[idx] = hv;
                    g_ml[idx] = __float2bfloat16(gv - __bfloat162float(hv));
                } else if (MODE == 4) {
                    int bb = z >> 3, hh = z & 7;
                    long idx = ((long)(bb * 1024 + gr)) * 2048 + hh * 256 + gc;
                    BF16 hv = __float2bfloat16(val);
                    g_oh[idx] = hv;
                    g_ol[idx] = __float2bfloat16(val - __bfloat162float(hv));
                }
            }
        }
}

// ---------------- layernorm (biased var, eps=1e-5) -> hi/lo ----------------
__global__ void ln_k(const float* __restrict__ x, const float* __restrict__ g,
                     const float* __restrict__ b,
                     BF16* __restrict__ oh, BF16* __restrict__ ol)
{
    const int r = blockIdx.x, t = threadIdx.x;   // 256 threads, D=256
    float v  = x[(long)r * 256 + t];
    float s  = v, s2 = v * v;
#pragma unroll
    for (int o = 16; o; o >>= 1) {
        s  += __shfl_xor_sync(0xffffffffu, s,  o);
        s2 += __shfl_xor_sync(0xffffffffu, s2, o);
    }
    __shared__ float sh1[8], sh2[8];
    if ((t & 31) == 0) { sh1[t >> 5] = s; sh2[t >> 5] = s2; }
    __syncthreads();
    float ts = 0.f, ts2 = 0.f;
#pragma unroll
    for (int i = 0; i < 8; i++) { ts += sh1[i]; ts2 += sh2[i]; }
    float mean = ts * (1.f / 256.f);
    float var  = ts2 * (1.f / 256.f) - mean * mean;
    float inv  = rsqrtf(var + 1e-5f);
    float y = (v - mean) * inv * g[t] + b[t];
    BF16 hv = __float2bfloat16(y);
    long idx = (long)r * 256 + t;
    oh[idx] = hv;
    ol[idx] = __float2bfloat16(y - __bfloat162float(hv));
}

// ---------------- softmax rows of 1024, folds /16, writes hi/lo ----------------
__global__ void softmax_k(const float* __restrict__ e,
                          BF16* __restrict__ ah, BF16* __restrict__ al)
{
    const long row = blockIdx.x;
    const int  t   = threadIdx.x;
    float4 v = *(reinterpret_cast<const float4*>(e) + row * 256 + t);
    float m = fmaxf(fmaxf(v.x, v.y), fmaxf(v.z, v.w));
#pragma unroll
    for (int o = 16; o; o >>= 1) m = fmaxf(m, __shfl_xor_sync(0xffffffffu, m, o));
    __shared__ float shm[8], shs[8];
    if ((t & 31) == 0) shm[t >> 5] = m;
    __syncthreads();
    m = shm[0];
#pragma unroll
    for (int i = 1; i < 8; i++) m = fmaxf(m, shm[i]);
    float e0 = expf(v.x - m), e1 = expf(v.y - m);
    float e2 = expf(v.z - m), e3 = expf(v.w - m);
    float s = e0 + e1 + e2 + e3;
#pragma unroll
    for (int o = 16; o; o >>= 1) s += __shfl_xor_sync(0xffffffffu, s, o);
    if ((t & 31) == 0) shs[t >> 5] = s;
    __syncthreads();
    float ts = 0.f;
#pragma unroll
    for (int i = 0; i < 8; i++) ts += shs[i];
    float sc = 1.f / (ts * 16.f);
    float p0 = e0 * sc, p1 = e1 * sc, p2 = e2 * sc, p3 = e3 * sc;
    BF16 h0 = __float2bfloat16(p0), h1 = __float2bfloat16(p1);
    BF16 h2 = __float2bfloat16(p2), h3 = __float2bfloat16(p3);
    long base = row * 1024 + t * 4;
    ah[base + 0] = h0; ah[base + 1] = h1; ah[base + 2] = h2; ah[base + 3] = h3;
    al[base + 0] = __float2bfloat16(p0 - __bfloat162float(h0));
    al[base + 1] = __float2bfloat16(p1 - __bfloat162float(h1));
    al[base + 2] = __float2bfloat16(p2 - __bfloat162float(h2));
    al[base + 3] = __float2bfloat16(p3 - __bfloat162float(h3));
}

// ---------------- fp32 -> bf16 hi/lo split (n4 = count of float4) ----------------
__global__ void cvt2_k(const float* __restrict__ in,
                       BF16* __restrict__ oh, BF16* __restrict__ ol, long n4)
{
    long i = (long)blockIdx.x * blockDim.x + threadIdx.x;
    if (i < n4) {
        float4 v = ((const float4*)in)[i];
        float f[4] = {v.x, v.y, v.z, v.w};
#pragma unroll
        for (int j = 0; j < 4; j++) {
            BF16 hv = __float2bfloat16(f[j]);
            oh[4 * i + j] = hv;
            ol[4 * i + j] = __float2bfloat16(f[j] - __bfloat162float(hv));
        }
    }
}

// ---------------- driver ----------------
extern "C" void kernel_launch(void* const* d_in, const int* in_sizes, int n_in,
                              void* d_out, int out_size)
{
    const float* x_in   = (const float*)d_in[0];
    const float* ln1_g  = (const float*)d_in[1];
    const float* ln1_b  = (const float*)d_in[2];
    const float* qkv_w  = (const float*)d_in[3];
    const float* qkv_b  = (const float*)d_in[4];
    const float* proj_w = (const float*)d_in[5];
    const float* proj_b = (const float*)d_in[6];
    const float* ln2_g  = (const float*)d_in[7];
    const float* ln2_b  = (const float*)d_in[8];
    const float* w1     = (const float*)d_in[9];
    const float* b1     = (const float*)d_in[10];
    const float* w2     = (const float*)d_in[11];
    const float* b2     = (const float*)d_in[12];
    float* x = (float*)d_out;

    float* pe;
    BF16 *phh, *phl, *pqh, *pql, *pkh, *pkl, *pvh, *pvl, *pah, *pal;
    BF16 *poh, *pol, *pmh, *pml;
    BF16 *pwqh, *pwql, *pwph, *pwpl, *pw1h, *pw1l, *pw2h, *pw2l;
    cudaGetSymbolAddress((void**)&pe,  g_e);
    cudaGetSymbolAddress((void**)&phh, g_hh);  cudaGetSymbolAddress((void**)&phl, g_hl);
    cudaGetSymbolAddress((void**)&pqh, g_qh);  cudaGetSymbolAddress((void**)&pql, g_ql);
    cudaGetSymbolAddress((void**)&pkh, g_kh);  cudaGetSymbolAddress((void**)&pkl, g_kl);
    cudaGetSymbolAddress((void**)&pvh, g_vh);  cudaGetSymbolAddress((void**)&pvl, g_vl);
    cudaGetSymbolAddress((void**)&pah, g_ah);  cudaGetSymbolAddress((void**)&pal, g_al);
    cudaGetSymbolAddress((void**)&poh, g_oh);  cudaGetSymbolAddress((void**)&pol, g_ol);
    cudaGetSymbolAddress((void**)&pmh, g_mh);  cudaGetSymbolAddress((void**)&pml, g_ml);
    cudaGetSymbolAddress((void**)&pwqh, g_wqh); cudaGetSymbolAddress((void**)&pwql, g_wql);
    cudaGetSymbolAddress((void**)&pwph, g_wph); cudaGetSymbolAddress((void**)&pwpl, g_wpl);
    cudaGetSymbolAddress((void**)&pw1h, g_w1h); cudaGetSymbolAddress((void**)&pw1l, g_w1l);
    cudaGetSymbolAddress((void**)&pw2h, g_w2h); cudaGetSymbolAddress((void**)&pw2l, g_w2l);

    cudaFuncSetAttribute(bgemm<0, true>,
                         cudaFuncAttributeMaxDynamicSharedMemorySize, SMEM_BYTES);
    cudaFuncSetAttribute(bgemm<1, false>,
                         cudaFuncAttributeMaxDynamicSharedMemorySize, SMEM_BYTES);
    cudaFuncSetAttribute(bgemm<2, false>,
                         cudaFuncAttributeMaxDynamicSharedMemorySize, SMEM_BYTES);
    cudaFuncSetAttribute(bgemm<3, false>,
                         cudaFuncAttributeMaxDynamicSharedMemorySize, SMEM_BYTES);
    cudaFuncSetAttribute(bgemm<4, false>,
                         cudaFuncAttributeMaxDynamicSharedMemorySize, SMEM_BYTES);

    cudaMemcpyAsync(x, x_in, (size_t)8192 * 256 * sizeof(float),
                    cudaMemcpyDeviceToDevice);

    // split all weights to bf16 hi/lo
    {
        long n;
        n = 4L * 256 * 6144 / 4; cvt2_k<<<(n + 255) / 256, 256>>>(qkv_w,  pwqh, pwql, n);
        n = 4L * 2048 * 256 / 4; cvt2_k<<<(n + 255) / 256, 256>>>(proj_w, pwph, pwpl, n);
        n = 4L * 256 * 1024 / 4; cvt2_k<<<(n + 255) / 256, 256>>>(w1, pw1h, pw1l, n);
        n = 4L * 1024 * 256 / 4; cvt2_k<<<(n + 255) / 256, 256>>>(w2, pw2h, pw2l, n);
    }

    for (int i = 0; i < 4; i++) {
        const BF16* qwh = pwqh + (long)i * 256 * 6144;
        const BF16* qwl = pwql + (long)i * 256 * 6144;
        const float* qb = qkv_b + i * 6144;
        const BF16* pwh = pwph + (long)i * 2048 * 256;
        const BF16* pwl = pwpl + (long)i * 2048 * 256;
        const float* pb = proj_b + i * 256;
        const BF16* w1ih = pw1h + (long)i * 256 * 1024;
        const BF16* w1il = pw1l + (long)i * 256 * 1024;
        const float* b1i = b1 + i * 1024;
        const BF16* w2ih = pw2h + (long)i * 1024 * 256;
        const BF16* w2il = pw2l + (long)i * 1024 * 256;
        const float* b2i = b2 + i * 256;

        // attention block
        ln_k<<<8192, 256>>>(x, ln1_g + i * 256, ln1_b + i * 256, phh, phl);
        bgemm<1, false><<<dim3(48, 64, 1), 256, SMEM_BYTES>>>(
            phh, phl, qwh, qwl, (float*)0, 256, 6144, 0, qb, 0, 0, 0);
        bgemm<0, true><<<dim3(8, 8, 64), 256, SMEM_BYTES>>>(
            pqh, pql, pkh, pkl, pe, 256, 256, 1024, (const float*)0,
            1024L * 256, 1024L * 256, 1024L * 1024);
        softmax_k<<<65536, 256>>>(pe, pah, pal);
        bgemm<4, false><<<dim3(2, 8, 64), 256, SMEM_BYTES>>>(
            pah, pal, pvh, pvl, (float*)0, 1024, 256, 0, (const float*)0,
            1024L * 1024, 1024L * 256, 0);
        bgemm<2, false><<<dim3(2, 64, 1), 256, SMEM_BYTES>>>(
            poh, pol, pwh, pwl, x, 2048, 256, 256, pb, 0, 0, 0);

        // MLP block
        ln_k<<<8192, 256>>>(x, ln2_g + i * 256, ln2_b + i * 256, phh, phl);
        bgemm<3, false><<<dim3(8, 64, 1), 256, SMEM_BYTES>>>(
            phh, phl, w1ih, w1il, (float*)0, 256, 1024, 1024, b1i, 0, 0, 0);
        bgemm<2, false><<<dim3(2, 64, 1), 256, SMEM_BYTES>>>(
            pmh, pml, w2ih, w2il, x, 1024, 256, 256, b2i, 0, 0, 0);
    }
}

// round 12
// speedup vs baseline: 1.8201x; 1.0027x over previous
#include <cuda_runtime.h>
#include <cuda_bf16.h>
#include <math.h>

typedef __nv_bfloat16 BF16;

// B=8, N=1024, D=256, H=8, d_head=256, HD=2048, M=1024, L=4
// rows BN = 8192, batch-heads BH = 64
// Round 12: 3-pass MMA reorder (break RAW chains), forced 2 CTA/SM occupancy,
//           MT=64 tile variant for proj/w2 grid fill.

// ---------------- static scratch ----------------
__device__ float g_e[64L * 1024 * 1024];     // 256 MB energy fp32
__device__ BF16 g_hh[8192L * 256];           // LN out hi
__device__ BF16 g_hl[8192L * 256];           // LN out lo
__device__ BF16 g_qh[64L * 1024 * 256];
__device__ BF16 g_ql[64L * 1024 * 256];
__device__ BF16 g_kh[64L * 1024 * 256];
__device__ BF16 g_kl[64L * 1024 * 256];
__device__ BF16 g_vh[64L * 1024 * 256];
__device__ BF16 g_vl[64L * 1024 * 256];
__device__ BF16 g_ah[64L * 1024 * 1024];     // attn hi
__device__ BF16 g_al[64L * 1024 * 1024];     // attn lo
__device__ BF16 g_oh[8192L * 2048];
__device__ BF16 g_ol[8192L * 2048];
__device__ BF16 g_mh[8192L * 1024];
__device__ BF16 g_ml[8192L * 1024];
__device__ BF16 g_wqh[4L * 256 * 6144];
__device__ BF16 g_wql[4L * 256 * 6144];
__device__ BF16 g_wph[4L * 2048 * 256];
__device__ BF16 g_wpl[4L * 2048 * 256];
__device__ BF16 g_w1h[4L * 256 * 1024];
__device__ BF16 g_w1l[4L * 256 * 1024];
__device__ BF16 g_w2h[4L * 1024 * 256];
__device__ BF16 g_w2l[4L * 1024 * 256];

// ---------------- asm helpers ----------------
__device__ __forceinline__ void ldm4(unsigned* r, unsigned addr) {
    asm volatile("ldmatrix.sync.aligned.m8n8.x4.shared.b16 {%0,%1,%2,%3}, [%4];"
                 : "=r"(r[0]), "=r"(r[1]), "=r"(r[2]), "=r"(r[3]) : "r"(addr));
}
__device__ __forceinline__ void ldm4t(unsigned* r, unsigned addr) {
    asm volatile("ldmatrix.sync.aligned.m8n8.x4.trans.shared.b16 {%0,%1,%2,%3}, [%4];"
                 : "=r"(r[0]), "=r"(r[1]), "=r"(r[2]), "=r"(r[3]) : "r"(addr));
}
__device__ __forceinline__ void mma16816(float* c, const unsigned* a,
                                         unsigned b0, unsigned b1) {
    asm volatile("mma.sync.aligned.m16n8k16.row.col.f32.bf16.bf16.f32 "
                 "{%0,%1,%2,%3}, {%4,%5,%6,%7}, {%8,%9}, {%0,%1,%2,%3};"
                 : "+f"(c[0]), "+f"(c[1]), "+f"(c[2]), "+f"(c[3])
                 : "r"(a[0]), "r"(a[1]), "r"(a[2]), "r"(a[3]),
                   "r"(b0), "r"(b1));
}
#define CPA(dst, src) asm volatile("cp.async.cg.shared.global [%0], [%1], 16;" :: "r"(dst), "l"(src))
#define CPC()  asm volatile("cp.async.commit_group;")
#define CPW0() asm volatile("cp.async.wait_group 0;")
#define CPW1() asm volatile("cp.async.wait_group 1;")

#define A_STRIDE 40
#define B_STRIDE 136
// smem per stage (stride 40960 B, total 81920 B):
//  +0      Ah   +10240 Al   +20480 Bh   +30720 Bl
#define SMEM_BYTES 81920

// ---------------- MTx128x32 3xBF16 tensor-core GEMM, cp.async double-buffered --
// MODE 0: fp32 store to g_e                 [energy]
// MODE 1: +bias, hi/lo scatter to q/k/v     [qkv]
// MODE 2: fp32 C += acc + bias              [proj, w2]
// MODE 3: hi/lo gelu(acc+bias) -> g_mh/g_ml [w1]
// MODE 4: hi/lo scatter to g_oh/g_ol        [attn@v]
// TRANSB: B stored [Ncols, K] row-major (compute A @ B^T); only with MT=128
// MT: row tile (128 or 64)
template<int MODE, bool TRANSB, int MT>
__global__ void __launch_bounds__(256, 2)
bgemm(const BF16* __restrict__ Ah, const BF16* __restrict__ Al,
      const BF16* __restrict__ Bh, const BF16* __restrict__ Bl,
      float* __restrict__ C, int K, int ldb, int ldc,
      const float* __restrict__ bias, long sA, long sB, long sC)
{
    extern __shared__ unsigned short sm[];
    const unsigned smBase = (unsigned)__cvta_generic_to_shared(sm);

    const int z = blockIdx.z;
    const BF16* Agh = Ah + (long)z * sA;
    const BF16* Agl = Al + (long)z * sA;
    const BF16* Bgh = Bh + (long)z * sB;
    const BF16* Bgl = Bl + (long)z * sB;
    float* Cg = C ? C + (long)z * sC : (float*)0;

    const int tid  = threadIdx.x;
    const int lane = tid & 31;
    const int warp = tid >> 5;
    constexpr int NB = (MT == 128) ? 8 : 4;   // n8 frags per warp
    constexpr int NI = NB / 2;                // 16-col ldmatrix tiles per warp
    const int wm = (MT == 128) ? (warp >> 1) : (warp >> 2);
    const int wn = (MT == 128) ? (warp & 1)  : (warp & 3);
    const int colOff = wn * (NB * 8);
    const int rowBase = blockIdx.y * MT;
    const int colBase = blockIdx.x * 128;

    float acc[2][NB][4];
#pragma unroll
    for (int i = 0; i < 2; i++)
#pragma unroll
        for (int j = 0; j < NB; j++)
#pragma unroll
            for (int e = 0; e < 4; e++) acc[i][j][e] = 0.f;

#define LOAD_TILE(k0, st) do {                                               \
    unsigned sb_ = smBase + (st) * 40960;                                    \
    _Pragma("unroll")                                                        \
    for (int u_ = 0; u_ < MT / 64; u_++) {                                   \
        int c_ = tid + u_ * 256;                                             \
        int r_ = c_ >> 2, k8_ = (c_ & 3) << 3;                               \
        CPA(sb_ + ((r_ * A_STRIDE + k8_) << 1),                              \
            Agh + (long)(rowBase + r_) * K + (k0) + k8_);                    \
        CPA(sb_ + 10240 + ((r_ * A_STRIDE + k8_) << 1),                      \
            Agl + (long)(rowBase + r_) * K + (k0) + k8_);                    \
    }                                                                        \
    _Pragma("unroll")                                                        \
    for (int u_ = 0; u_ < 2; u_++) {                                         \
        int c_ = tid + u_ * 256;                                             \
        if (TRANSB) {                                                        \
            int r_ = c_ >> 2, k8_ = (c_ & 3) << 3;                           \
            CPA(sb_ + 20480 + ((r_ * A_STRIDE + k8_) << 1),                  \
                Bgh + (long)(colBase + r_) * ldb + (k0) + k8_);              \
            CPA(sb_ + 30720 + ((r_ * A_STRIDE + k8_) << 1),                  \
                Bgl + (long)(colBase + r_) * ldb + (k0) + k8_);              \
        } else {                                                             \
            int kk_ = c_ >> 4, n8_ = (c_ & 15) << 3;                         \
            CPA(sb_ + 20480 + ((kk_ * B_STRIDE + n8_) << 1),                 \
                Bgh + (long)((k0) + kk_) * ldb + colBase + n8_);             \
            CPA(sb_ + 30720 + ((kk_ * B_STRIDE + n8_) << 1),                 \
                Bgl + (long)((k0) + kk_) * ldb + colBase + n8_);             \
        }                                                                    \
    }                                                                        \
} while (0)

    const int nk = K >> 5;
    LOAD_TILE(0, 0);
    CPC();

    for (int kt = 0; kt < nk; kt++) {
        if (kt + 1 < nk) {
            LOAD_TILE((kt + 1) << 5, (kt + 1) & 1);
            CPC();
            CPW1();
        } else {
            CPW0();
        }
        __syncthreads();

        const unsigned sb = smBase + (kt & 1) * 40960;
#pragma unroll
        for (int ks = 0; ks < 2; ks++) {
            unsigned fah[2][4], fal[2][4], fbh[NI][4], fbl[NI][4];
            // A-hi and B-hi fragments
#pragma unroll
            for (int mi = 0; mi < 2; mi++) {
                unsigned off = ((unsigned)((wm * 32 + mi * 16 + (lane & 15)) * A_STRIDE
                                + ks * 16 + ((lane >> 4) << 3))) << 1;
                ldm4(fah[mi], sb + off);
            }
#pragma unroll
            for (int ni = 0; ni < NI; ni++) {
                if (TRANSB) {
                    unsigned off = ((unsigned)((colOff + ni * 16 + (lane & 15)) * A_STRIDE
                                    + ks * 16 + ((lane >> 4) << 3))) << 1;
                    ldm4(fbh[ni], sb + 20480 + off);
                } else {
                    unsigned off = ((unsigned)((ks * 16 + (lane & 15)) * B_STRIDE
                                    + colOff + ni * 16 + ((lane >> 4) << 3))) << 1;
                    ldm4t(fbh[ni], sb + 20480 + off);
                }
            }
            // pass 1: hi * hi  (16 independent accumulators -> no RAW chains)
#pragma unroll
            for (int mi = 0; mi < 2; mi++)
#pragma unroll
                for (int nb = 0; nb < NB; nb++) {
                    int ti = nb >> 1;
                    unsigned b0, b1;
                    if (TRANSB) { b0 = fbh[ti][nb & 1]; b1 = fbh[ti][(nb & 1) + 2]; }
                    else        { b0 = fbh[ti][(nb & 1) * 2]; b1 = fbh[ti][(nb & 1) * 2 + 1]; }
                    mma16816(acc[mi][nb], fah[mi], b0, b1);
                }
            // B-lo fragments, pass 2: hi * lo
#pragma unroll
            for (int ni = 0; ni < NI; ni++) {
                if (TRANSB) {
                    unsigned off = ((unsigned)((colOff + ni * 16 + (lane & 15)) * A_STRIDE
                                    + ks * 16 + ((lane >> 4) << 3))) << 1;
                    ldm4(fbl[ni], sb + 30720 + off);
                } else {
                    unsigned off = ((unsigned)((ks * 16 + (lane & 15)) * B_STRIDE
                                    + colOff + ni * 16 + ((lane >> 4) << 3))) << 1;
                    ldm4t(fbl[ni], sb + 30720 + off);
                }
            }
#pragma unroll
            for (int mi = 0; mi < 2; mi++)
#pragma unroll
                for (int nb = 0; nb < NB; nb++) {
                    int ti = nb >> 1;
                    unsigned b0, b1;
                    if (TRANSB) { b0 = fbl[ti][nb & 1]; b1 = fbl[ti][(nb & 1) + 2]; }
                    else        { b0 = fbl[ti][(nb & 1) * 2]; b1 = fbl[ti][(nb & 1) * 2 + 1]; }
                    mma16816(acc[mi][nb], fah[mi], b0, b1);
                }
            // A-lo fragments, pass 3: lo * hi
#pragma unroll
            for (int mi = 0; mi < 2; mi++) {
                unsigned off = ((unsigned)((wm * 32 + mi * 16 + (lane & 15)) * A_STRIDE
                                + ks * 16 + ((lane >> 4) << 3))) << 1;
                ldm4(fal[mi], sb + 10240 + off);
            }
#pragma unroll
            for (int mi = 0; mi < 2; mi++)
#pragma unroll
                for (int nb = 0; nb < NB; nb++) {
                    int ti = nb >> 1;
                    unsigned b0, b1;
                    if (TRANSB) { b0 = fbh[ti][nb & 1]; b1 = fbh[ti][(nb & 1) + 2]; }
                    else        { b0 = fbh[ti][(nb & 1) * 2]; b1 = fbh[ti][(nb & 1) * 2 + 1]; }
                    mma16816(acc[mi][nb], fal[mi], b0, b1);
                }
        }
        __syncthreads();
    }
#undef LOAD_TILE

    // ---------------- epilogue ----------------
    const int g  = lane >> 2;
    const int tg = lane & 3;
#pragma unroll
    for (int mi = 0; mi < 2; mi++)
#pragma unroll
        for (int nb = 0; nb < NB; nb++) {
            int r0 = rowBase + wm * 32 + mi * 16 + g;
            int c0 = colBase + colOff + nb * 8 + tg * 2;
#pragma unroll
            for (int e = 0; e < 4; e++) {
                int gr = r0 + (e >> 1) * 8;
                int gc = c0 + (e & 1);
                float val = acc[mi][nb][e];
                if (MODE == 0) {
                    Cg[(long)gr * ldc + gc] = val;
                } else if (MODE == 1) {
                    float xv = val + bias[gc];
                    int which = gc % 3, cc = gc / 3;
                    int dd = cc & 255, hh = cc >> 8;
                    int bb = gr >> 10, n = gr & 1023;
                    long idx = ((long)((bb << 3) + hh) * 1024 + n) * 256 + dd;
                    BF16 hv = __float2bfloat16(xv);
                    BF16 lv = __float2bfloat16(xv - __bfloat162float(hv));
                    if (which == 0)      { g_qh[idx] = hv; g_ql[idx] = lv; }
                    else if (which == 1) { g_kh[idx] = hv; g_kl[idx] = lv; }
                    else                 { g_vh[idx] = hv; g_vl[idx] = lv; }
                } else if (MODE == 2) {
                    Cg[(long)gr * ldc + gc] += val + bias[gc];
                } else if (MODE == 3) {
                    float t = val + bias[gc];
                    float gv = 0.5f * t * (1.f + erff(t * 0.70710678118654752f));
                    long idx = (long)gr * ldc + gc;
                    BF16 hv = __float2bfloat16(gv);
                    g_mh[idx] = hv;
                    g_ml[idx] = __float2bfloat16(gv - __bfloat162float(hv));
                } else if (MODE == 4) {
                    int bb = z >> 3, hh = z & 7;
                    long idx = ((long)(bb * 1024 + gr)) * 2048 + hh * 256 + gc;
                    BF16 hv = __float2bfloat16(val);
                    g_oh[idx] = hv;
                    g_ol[idx] = __float2bfloat16(val - __bfloat162float(hv));
                }
            }
        }
}

// ---------------- layernorm (biased var, eps=1e-5) -> hi/lo ----------------
__global__ void ln_k(const float* __restrict__ x, const float* __restrict__ g,
                     const float* __restrict__ b,
                     BF16* __restrict__ oh, BF16* __restrict__ ol)
{
    const int r = blockIdx.x, t = threadIdx.x;   // 256 threads, D=256
    float v  = x[(long)r * 256 + t];
    float s  = v, s2 = v * v;
#pragma unroll
    for (int o = 16; o; o >>= 1) {
        s  += __shfl_xor_sync(0xffffffffu, s,  o);
        s2 += __shfl_xor_sync(0xffffffffu, s2, o);
    }
    __shared__ float sh1[8], sh2[8];
    if ((t & 31) == 0) { sh1[t >> 5] = s; sh2[t >> 5] = s2; }
    __syncthreads();
    float ts = 0.f, ts2 = 0.f;
#pragma unroll
    for (int i = 0; i < 8; i++) { ts += sh1[i]; ts2 += sh2[i]; }
    float mean = ts * (1.f / 256.f);
    float var  = ts2 * (1.f / 256.f) - mean * mean;
    float inv  = rsqrtf(var + 1e-5f);
    float y = (v - mean) * inv * g[t] + b[t];
    BF16 hv = __float2bfloat16(y);
    long idx = (long)r * 256 + t;
    oh[idx] = hv;
    ol[idx] = __float2bfloat16(y - __bfloat162float(hv));
}

// ---------------- softmax rows of 1024, folds /16, writes hi/lo ----------------
__global__ void softmax_k(const float* __restrict__ e,
                          BF16* __restrict__ ah, BF16* __restrict__ al)
{
    const long row = blockIdx.x;
    const int  t   = threadIdx.x;
    float4 v = *(reinterpret_cast<const float4*>(e) + row * 256 + t);
    float m = fmaxf(fmaxf(v.x, v.y), fmaxf(v.z, v.w));
#pragma unroll
    for (int o = 16; o; o >>= 1) m = fmaxf(m, __shfl_xor_sync(0xffffffffu, m, o));
    __shared__ float shm[8], shs[8];
    if ((t & 31) == 0) shm[t >> 5] = m;
    __syncthreads();
    m = shm[0];
#pragma unroll
    for (int i = 1; i < 8; i++) m = fmaxf(m, shm[i]);
    float e0 = expf(v.x - m), e1 = expf(v.y - m);
    float e2 = expf(v.z - m), e3 = expf(v.w - m);
    float s = e0 + e1 + e2 + e3;
#pragma unroll
    for (int o = 16; o; o >>= 1) s += __shfl_xor_sync(0xffffffffu, s, o);
    if ((t & 31) == 0) shs[t >> 5] = s;
    __syncthreads();
    float ts = 0.f;
#pragma unroll
    for (int i = 0; i < 8; i++) ts += shs[i];
    float sc = 1.f / (ts * 16.f);
    float p0 = e0 * sc, p1 = e1 * sc, p2 = e2 * sc, p3 = e3 * sc;
    BF16 h0 = __float2bfloat16(p0), h1 = __float2bfloat16(p1);
    BF16 h2 = __float2bfloat16(p2), h3 = __float2bfloat16(p3);
    long base = row * 1024 + t * 4;
    ah[base + 0] = h0; ah[base + 1] = h1; ah[base + 2] = h2; ah[base + 3] = h3;
    al[base + 0] = __float2bfloat16(p0 - __bfloat162float(h0));
    al[base + 1] = __float2bfloat16(p1 - __bfloat162float(h1));
    al[base + 2] = __float2bfloat16(p2 - __bfloat162float(h2));
    al[base + 3] = __float2bfloat16(p3 - __bfloat162float(h3));
}

// ---------------- fp32 -> bf16 hi/lo split (n4 = count of float4) ----------------
__global__ void cvt2_k(const float* __restrict__ in,
                       BF16* __restrict__ oh, BF16* __restrict__ ol, long n4)
{
    long i = (long)blockIdx.x * blockDim.x + threadIdx.x;
    if (i < n4) {
        float4 v = ((const float4*)in)[i];
        float f[4] = {v.x, v.y, v.z, v.w};
#pragma unroll
        for (int j = 0; j < 4; j++) {
            BF16 hv = __float2bfloat16(f[j]);
            oh[4 * i + j] = hv;
            ol[4 * i + j] = __float2bfloat16(f[j] - __bfloat162float(hv));
        }
    }
}

// ---------------- driver ----------------
extern "C" void kernel_launch(void* const* d_in, const int* in_sizes, int n_in,
                              void* d_out, int out_size)
{
    const float* x_in   = (const float*)d_in[0];
    const float* ln1_g  = (const float*)d_in[1];
    const float* ln1_b  = (const float*)d_in[2];
    const float* qkv_w  = (const float*)d_in[3];
    const float* qkv_b  = (const float*)d_in[4];
    const float* proj_w = (const float*)d_in[5];
    const float* proj_b = (const float*)d_in[6];
    const float* ln2_g  = (const float*)d_in[7];
    const float* ln2_b  = (const float*)d_in[8];
    const float* w1     = (const float*)d_in[9];
    const float* b1     = (const float*)d_in[10];
    const float* w2     = (const float*)d_in[11];
    const float* b2     = (const float*)d_in[12];
    float* x = (float*)d_out;

    float* pe;
    BF16 *phh, *phl, *pqh, *pql, *pkh, *pkl, *pvh, *pvl, *pah, *pal;
    BF16 *poh, *pol, *pmh, *pml;
    BF16 *pwqh, *pwql, *pwph, *pwpl, *pw1h, *pw1l, *pw2h, *pw2l;
    cudaGetSymbolAddress((void**)&pe,  g_e);
    cudaGetSymbolAddress((void**)&phh, g_hh);  cudaGetSymbolAddress((void**)&phl, g_hl);
    cudaGetSymbolAddress((void**)&pqh, g_qh);  cudaGetSymbolAddress((void**)&pql, g_ql);
    cudaGetSymbolAddress((void**)&pkh, g_kh);  cudaGetSymbolAddress((void**)&pkl, g_kl);
    cudaGetSymbolAddress((void**)&pvh, g_vh);  cudaGetSymbolAddress((void**)&pvl, g_vl);
    cudaGetSymbolAddress((void**)&pah, g_ah);  cudaGetSymbolAddress((void**)&pal, g_al);
    cudaGetSymbolAddress((void**)&poh, g_oh);  cudaGetSymbolAddress((void**)&pol, g_ol);
    cudaGetSymbolAddress((void**)&pmh, g_mh);  cudaGetSymbolAddress((void**)&pml, g_ml);
    cudaGetSymbolAddress((void**)&pwqh, g_wqh); cudaGetSymbolAddress((void**)&pwql, g_wql);
    cudaGetSymbolAddress((void**)&pwph, g_wph); cudaGetSymbolAddress((void**)&pwpl, g_wpl);
    cudaGetSymbolAddress((void**)&pw1h, g_w1h); cudaGetSymbolAddress((void**)&pw1l, g_w1l);
    cudaGetSymbolAddress((void**)&pw2h, g_w2h); cudaGetSymbolAddress((void**)&pw2l, g_w2l);

    cudaFuncSetAttribute(bgemm<0, true, 128>,
                         cudaFuncAttributeMaxDynamicSharedMemorySize, SMEM_BYTES);
    cudaFuncSetAttribute(bgemm<1, false, 128>,
                         cudaFuncAttributeMaxDynamicSharedMemorySize, SMEM_BYTES);
    cudaFuncSetAttribute(bgemm<2, false, 64>,
                         cudaFuncAttributeMaxDynamicSharedMemorySize, SMEM_BYTES);
    cudaFuncSetAttribute(bgemm<3, false, 128>,
                         cudaFuncAttributeMaxDynamicSharedMemorySize, SMEM_BYTES);
    cudaFuncSetAttribute(bgemm<4, false, 128>,
                         cudaFuncAttributeMaxDynamicSharedMemorySize, SMEM_BYTES);

    cudaMemcpyAsync(x, x_in, (size_t)8192 * 256 * sizeof(float),
                    cudaMemcpyDeviceToDevice);

    // split all weights to bf16 hi/lo
    {
        long n;
        n = 4L * 256 * 6144 / 4; cvt2_k<<<(n + 255) / 256, 256>>>(qkv_w,  pwqh, pwql, n);
        n = 4L * 2048 * 256 / 4; cvt2_k<<<(n + 255) / 256, 256>>>(proj_w, pwph, pwpl, n);
        n = 4L * 256 * 1024 / 4; cvt2_k<<<(n + 255) / 256, 256>>>(w1, pw1h, pw1l, n);
        n = 4L * 1024 * 256 / 4; cvt2_k<<<(n + 255) / 256, 256>>>(w2, pw2h, pw2l, n);
    }

    for (int i = 0; i < 4; i++) {
        const BF16* qwh = pwqh + (long)i * 256 * 6144;
        const BF16* qwl = pwql + (long)i * 256 * 6144;
        const float* qb = qkv_b + i * 6144;
        const BF16* pwh = pwph + (long)i * 2048 * 256;
        const BF16* pwl = pwpl + (long)i * 2048 * 256;
        const float* pb = proj_b + i * 256;
        const BF16* w1ih = pw1h + (long)i * 256 * 1024;
        const BF16* w1il = pw1l + (long)i * 256 * 1024;
        const float* b1i = b1 + i * 1024;
        const BF16* w2ih = pw2h + (long)i * 1024 * 256;
        const BF16* w2il = pw2l + (long)i * 1024 * 256;
        const float* b2i = b2 + i * 256;

        // attention block
        ln_k<<<8192, 256>>>(x, ln1_g + i * 256, ln1_b + i * 256, phh, phl);
        bgemm<1, false, 128><<<dim3(48, 64, 1), 256, SMEM_BYTES>>>(
            phh, phl, qwh, qwl, (float*)0, 256, 6144, 0, qb, 0, 0, 0);
        bgemm<0, true, 128><<<dim3(8, 8, 64), 256, SMEM_BYTES>>>(
            pqh, pql, pkh, pkl, pe, 256, 256, 1024, (const float*)0,
            1024L * 256, 1024L * 256, 1024L * 1024);
        softmax_k<<<65536, 256>>>(pe, pah, pal);
        bgemm<4, false, 128><<<dim3(2, 8, 64), 256, SMEM_BYTES>>>(
            pah, pal, pvh, pvl, (float*)0, 1024, 256, 0, (const float*)0,
            1024L * 1024, 1024L * 256, 0);
        bgemm<2, false, 64><<<dim3(2, 128, 1), 256, SMEM_BYTES>>>(
            poh, pol, pwh, pwl, x, 2048, 256, 256, pb, 0, 0, 0);

        // MLP block
        ln_k<<<8192, 256>>>(x, ln2_g + i * 256, ln2_b + i * 256, phh, phl);
        bgemm<3, false, 128><<<dim3(8, 64, 1), 256, SMEM_BYTES>>>(
            phh, phl, w1ih, w1il, (float*)0, 256, 1024, 1024, b1i, 0, 0, 0);
        bgemm<2, false, 64><<<dim3(2, 128, 1), 256, SMEM_BYTES>>>(
            pmh, pml, w2ih, w2il, x, 1024, 256, 256, b2i, 0, 0, 0);
    }
}